// round 7
// baseline (speedup 1.0000x reference)
#include <cuda_runtime.h>
#include <cuda_bf16.h>
#include <cstdint>

#define NB    16
#define NDIM  128
#define NPTS  16384
#define NJ    16
#define NR    8
#define KT    32                     // K-tile depth
#define ROWPAD 40                    // padded smem row (elements)
#define TILE_B (128 * ROWPAD * 2)    // 10240 bytes per bf16 tile
#define BUF_B  (4 * TILE_B)          // Ah|Al|Bh|Bl = 40960
#define SMEM_B (2 * BUF_B)           // double buffer = 81920

typedef __nv_bfloat16 bf16;

// ---------------- device scratch ----------------
__device__ __align__(16) float g_xhatT[NB * 128 * 128];      // [b][l][i]  1 MB
__device__ __align__(16) float g_y    [NB * 128 * 128];      // [(b,o)][k] 1 MB
__device__ __align__(16) bf16 g_xhT_h[NB * 128 * 128], g_xhT_l[NB * 128 * 128];
__device__ __align__(16) bf16 g_Wt_h [NJ * 128 * 128], g_Wt_l [NJ * 128 * 128];   // [j][o][i]
__device__ __align__(16) bf16 g_Hk_h [128 * NJ * 128], g_Hk_l [128 * NJ * 128];   // [k][(j,l)]
__device__ __align__(16) bf16 g_z_h  [2048 * 2048],    g_z_l  [2048 * 2048];      // [(b,o)][(j,l)]
__device__ __align__(16) bf16 g_y_h  [2048 * 128],     g_y_l  [2048 * 128];
__device__ __align__(16) bf16 g_wbT_h[128 * NPTS],     g_wbT_l[128 * NPTS];       // [l][x]
__device__ __align__(16) bf16 g_bs_h [NPTS * 128],     g_bs_l [NPTS * 128];       // [x][k]

// ---------------- helpers ----------------
__device__ __forceinline__ uint32_t smem_u32(const void* p) {
    uint32_t a;
    asm("{ .reg .u64 t; cvta.to.shared.u64 t, %1; cvt.u32.u64 %0, t; }" : "=r"(a) : "l"(p));
    return a;
}
__device__ __forceinline__ void cp16(uint32_t dst, const void* src) {
    asm volatile("cp.async.cg.shared.global [%0], [%1], 16;" :: "r"(dst), "l"(src));
}
__device__ __forceinline__ void cp_commit() {
    asm volatile("cp.async.commit_group;" ::: "memory");
}
template <int N>
__device__ __forceinline__ void cp_wait() {
    asm volatile("cp.async.wait_group %0;" :: "n"(N) : "memory");
}
__device__ __forceinline__ void ldmx4(uint32_t* r, uint32_t addr) {
    asm volatile("ldmatrix.sync.aligned.m8n8.x4.shared.b16 {%0,%1,%2,%3}, [%4];"
                 : "=r"(r[0]), "=r"(r[1]), "=r"(r[2]), "=r"(r[3]) : "r"(addr));
}
__device__ __forceinline__ void mma_bf16(float* c, const uint32_t* a, const uint32_t* b) {
    asm volatile("mma.sync.aligned.m16n8k16.row.col.f32.bf16.bf16.f32 "
                 "{%0,%1,%2,%3}, {%4,%5,%6,%7}, {%8,%9}, {%0,%1,%2,%3};"
                 : "+f"(c[0]), "+f"(c[1]), "+f"(c[2]), "+f"(c[3])
                 : "r"(a[0]), "r"(a[1]), "r"(a[2]), "r"(a[3]), "r"(b[0]), "r"(b[1]));
}
// fp32x4 -> bf16 hi pair + lo (residual) pair
__device__ __forceinline__ void cvt_hl(float4 v, uint2& hi, uint2& lo) {
    __nv_bfloat162 h0 = __floats2bfloat162_rn(v.x, v.y);
    __nv_bfloat162 h1 = __floats2bfloat162_rn(v.z, v.w);
    uint32_t u0 = *(uint32_t*)&h0, u1 = *(uint32_t*)&h1;
    float rx = v.x - __uint_as_float(u0 << 16);
    float ry = v.y - __uint_as_float(u0 & 0xffff0000u);
    float rz = v.z - __uint_as_float(u1 << 16);
    float rw = v.w - __uint_as_float(u1 & 0xffff0000u);
    __nv_bfloat162 l0 = __floats2bfloat162_rn(rx, ry);
    __nv_bfloat162 l1 = __floats2bfloat162_rn(rz, rw);
    hi = make_uint2(u0, u1);
    lo = make_uint2(*(uint32_t*)&l0, *(uint32_t*)&l1);
}
__device__ __forceinline__ void split1(float v, bf16& h, bf16& l) {
    h = __float2bfloat16(v);
    l = __float2bfloat16(v - __bfloat162float(h));
}
// pack two fp32 into bf16x2 hi word + lo word
__device__ __forceinline__ void split2(float a, float b, uint32_t& hw, uint32_t& lw) {
    __nv_bfloat162 h = __floats2bfloat162_rn(a, b);
    uint32_t u = *(uint32_t*)&h;
    float ra = a - __uint_as_float(u << 16);
    float rb = b - __uint_as_float(u & 0xffff0000u);
    __nv_bfloat162 l = __floats2bfloat162_rn(ra, rb);
    hw = u;
    lw = *(uint32_t*)&l;
}

// ---------------- shared compute: one 32-deep K tile ----------------
__device__ __forceinline__ void compute_kt(uint32_t bb, float acc[16][4],
                                           int a_off, int b_off, int wr, int wc) {
#pragma unroll
    for (int ks = 0; ks < 2; ++ks) {
        const uint32_t koff = ks * 32;        // 16 elements * 2B
        uint32_t bh[4][2], bl[4][2];
#pragma unroll
        for (int n2 = 0; n2 < 2; ++n2) {
            const uint32_t nbase = (wc * 32 + n2 * 16) * 80 + koff + b_off;
            uint32_t r4[4];
            ldmx4(r4, bb + 2 * TILE_B + nbase);
            bh[n2 * 2][0] = r4[0]; bh[n2 * 2][1] = r4[1];
            bh[n2 * 2 + 1][0] = r4[2]; bh[n2 * 2 + 1][1] = r4[3];
            ldmx4(r4, bb + 3 * TILE_B + nbase);
            bl[n2 * 2][0] = r4[0]; bl[n2 * 2][1] = r4[1];
            bl[n2 * 2 + 1][0] = r4[2]; bl[n2 * 2 + 1][1] = r4[3];
        }
#pragma unroll
        for (int mi = 0; mi < 4; ++mi) {
            const uint32_t mbase = (wr * 64 + mi * 16) * 80 + koff + a_off;
            uint32_t ah[4], al[4];
            ldmx4(ah, bb + 0 * TILE_B + mbase);
            ldmx4(al, bb + 1 * TILE_B + mbase);
#pragma unroll
            for (int ni = 0; ni < 4; ++ni) {
                mma_bf16(acc[mi * 4 + ni], ah, bh[ni]);
                mma_bf16(acc[mi * 4 + ni], ah, bl[ni]);
                mma_bf16(acc[mi * 4 + ni], al, bh[ni]);
            }
        }
    }
}

// issue cp.async for one pre-split bf16 tile (2 chunks/thread)
__device__ __forceinline__ void issue_tile(uint32_t bb, int tile, const bf16* base,
                                           int ld, int k0, int t) {
    int cit = t;
    int row = cit >> 2, q = cit & 3;
    cp16(bb + tile * TILE_B + row * 80 + q * 16, base + (size_t)row * ld + k0 + q * 8);
    cit = t + 256; row = cit >> 2; q = cit & 3;
    cp16(bb + tile * TILE_B + row * 80 + q * 16, base + (size_t)row * ld + k0 + q * 8);
}

// ---------------- pure pre-split bf16 core ----------------
__device__ __forceinline__ void mm_bf16_core(const bf16* __restrict__ Ah,
                                             const bf16* __restrict__ Al, int lda,
                                             const bf16* __restrict__ Bh,
                                             const bf16* __restrict__ Bl, int ldb,
                                             int ktiles, float acc[16][4]) {
    extern __shared__ __align__(128) char dsm[];
    const int t = threadIdx.x, lane = t & 31, w = t >> 5;
    const int wr = w >> 2, wc = w & 3;
    const uint32_t sb = smem_u32(dsm);
    const int a_off = ((lane & 7) + ((lane >> 3) & 1) * 8) * 80 + ((lane >> 4) & 1) * 16;
    const int b_off = ((lane & 7) + ((lane >> 4) & 1) * 8) * 80 + ((lane >> 3) & 1) * 16;

#pragma unroll
    for (int i = 0; i < 16; ++i)
#pragma unroll
        for (int j = 0; j < 4; ++j) acc[i][j] = 0.0f;

    issue_tile(sb, 0, Ah, lda, 0, t);
    issue_tile(sb, 1, Al, lda, 0, t);
    issue_tile(sb, 2, Bh, ldb, 0, t);
    issue_tile(sb, 3, Bl, ldb, 0, t);
    cp_commit();

    int cur = 0;
    for (int kt = 0; kt < ktiles; ++kt) {
        const bool more = (kt + 1 < ktiles);
        if (more) {
            const uint32_t nb = sb + (cur ^ 1) * BUF_B;
            const int k0 = (kt + 1) * KT;
            issue_tile(nb, 0, Ah, lda, k0, t);
            issue_tile(nb, 1, Al, lda, k0, t);
            issue_tile(nb, 2, Bh, ldb, k0, t);
            issue_tile(nb, 3, Bl, ldb, k0, t);
            cp_commit();
            cp_wait<1>();
        } else {
            cp_wait<0>();
        }
        __syncthreads();
        compute_kt(sb + cur * BUF_B, acc, a_off, b_off, wr, wc);
        __syncthreads();
        cur ^= 1;
    }
}

// ---------------- mixed core: A fp32 (in-kernel split), B pre-split ----------------
__device__ __forceinline__ void mm_af32_core(const float* __restrict__ A, int lda,
                                             const bf16* __restrict__ Bh,
                                             const bf16* __restrict__ Bl, int ldb,
                                             int ktiles, float acc[16][4]) {
    extern __shared__ __align__(128) char dsm[];
    const int t = threadIdx.x, lane = t & 31, w = t >> 5;
    const int wr = w >> 2, wc = w & 3;
    const uint32_t sb = smem_u32(dsm);
    const int a_off = ((lane & 7) + ((lane >> 3) & 1) * 8) * 80 + ((lane >> 4) & 1) * 16;
    const int b_off = ((lane & 7) + ((lane >> 4) & 1) * 8) * 80 + ((lane >> 3) & 1) * 16;
    const int ar = t >> 1, ac4 = (t & 1) * 4;      // unused alt mapping guard

#pragma unroll
    for (int i = 0; i < 16; ++i)
#pragma unroll
        for (int j = 0; j < 4; ++j) acc[i][j] = 0.0f;

    float4 av[4];
    // prologue tile 0
    issue_tile(sb, 2, Bh, ldb, 0, t);
    issue_tile(sb, 3, Bl, ldb, 0, t);
    cp_commit();
#pragma unroll
    for (int i = 0; i < 4; ++i) {
        const int idx = t + 256 * i, r = idx >> 3, c4 = (idx & 7) << 2;
        av[i] = *(const float4*)&A[(size_t)r * lda + c4];
    }
#pragma unroll
    for (int i = 0; i < 4; ++i) {
        const int idx = t + 256 * i, r = idx >> 3, c4 = (idx & 7) << 2;
        const uint32_t eo = r * 80 + c4 * 2;
        uint2 hi, lo;
        cvt_hl(av[i], hi, lo);
        *(uint2*)(dsm + 0 * TILE_B + eo) = hi;
        *(uint2*)(dsm + 1 * TILE_B + eo) = lo;
    }

    int cur = 0;
    for (int kt = 0; kt < ktiles; ++kt) {
        const bool more = (kt + 1 < ktiles);
        if (more) {
#pragma unroll
            for (int i = 0; i < 4; ++i) {
                const int idx = t + 256 * i, r = idx >> 3, c4 = (idx & 7) << 2;
                av[i] = *(const float4*)&A[(size_t)r * lda + (kt + 1) * KT + c4];
            }
            const uint32_t nb = sb + (cur ^ 1) * BUF_B;
            issue_tile(nb, 2, Bh, ldb, (kt + 1) * KT, t);
            issue_tile(nb, 3, Bl, ldb, (kt + 1) * KT, t);
            cp_commit();
            cp_wait<1>();
        } else {
            cp_wait<0>();
        }
        __syncthreads();
        compute_kt(sb + cur * BUF_B, acc, a_off, b_off, wr, wc);
        __syncthreads();
        if (more) {
            const int nxt = cur ^ 1;
#pragma unroll
            for (int i = 0; i < 4; ++i) {
                const int idx = t + 256 * i, r = idx >> 3, c4 = (idx & 7) << 2;
                const uint32_t eo = nxt * BUF_B + r * 80 + c4 * 2;
                uint2 hi, lo;
                cvt_hl(av[i], hi, lo);
                *(uint2*)(dsm + eo + 0 * TILE_B) = hi;
                *(uint2*)(dsm + eo + 1 * TILE_B) = lo;
            }
        }
        cur ^= 1;
    }
    (void)ar; (void)ac4;
}

// ---------------- prep kernels ----------------
__global__ void zero_kernel() {
    int i = blockIdx.x * 256 + threadIdx.x;   // 262144 each
    g_xhatT[i] = 0.0f;
    g_y[i]     = 0.0f;
}

__global__ void __launch_bounds__(256) ht_kernel(const float* __restrict__ Aop,
                                                 const float* __restrict__ Bop,
                                                 const float* __restrict__ Dout,
                                                 const float* __restrict__ Din,
                                                 const float* __restrict__ product) {
    int j = blockIdx.x;
    int t = threadIdx.x;
    __shared__ float Aj[NR * 64];
    __shared__ float Bj[NR * 64];
    __shared__ float Qs[64 * 64];
    for (int i = t; i < NR * 64; i += 256) {
        Aj[i] = Aop[j * (NR * 64) + i];
        Bj[i] = Bop[j * (NR * 64) + i];
    }
    __syncthreads();
#pragma unroll
    for (int s = 0; s < 16; ++s) {
        int idx = t + 256 * s;
        int m = idx >> 6, n = idx & 63;
        float q = 0.0f;
#pragma unroll
        for (int r = 0; r < NR; ++r) q += Aj[r * 64 + m] * Bj[r * 64 + n];
        Qs[idx] = q;
    }
    __syncthreads();
#pragma unroll 4
    for (int s = 0; s < 64; ++s) {
        int idx = t + 256 * s;        // 16384 = 128x128
        int k = idx >> 7, l = idx & 127;
        float h = Dout[j * 128 + k] * Din[j * 128 + l] * product[k * 128 + l];
        if (k < 64 && l < 64) h += Qs[k * 64 + l];
        bf16 hh, ll;
        split1(h, hh, ll);
        g_Hk_h[k * (NJ * 128) + j * 128 + l] = hh;
        g_Hk_l[k * (NJ * 128) + j * 128 + l] = ll;
    }
}

__global__ void wt_kernel(const float* __restrict__ w) {
    int id = blockIdx.x * 256 + threadIdx.x;   // 262144
    int ii = id & 127;
    int o  = (id >> 7) & 127;
    int j  = id >> 14;
    bf16 h, l;
    split1(w[(ii * 128 + o) * NJ + j], h, l);
    g_Wt_h[id] = h;
    g_Wt_l[id] = l;
}

// wbases[NPTS][128] -> wbT hi/lo [128][NPTS]
__global__ void __launch_bounds__(256) twb_kernel(const float* __restrict__ wb) {
    __shared__ float tile[32][33];
    int xb = blockIdx.x * 32, kb = blockIdx.y * 32;
    int tx = threadIdx.x & 31, ty = threadIdx.x >> 5;
#pragma unroll
    for (int i = 0; i < 32; i += 8)
        tile[ty + i][tx] = wb[(size_t)(xb + ty + i) * 128 + kb + tx];
    __syncthreads();
#pragma unroll
    for (int i = 0; i < 32; i += 8) {
        bf16 h, l;
        split1(tile[tx][ty + i], h, l);
        g_wbT_h[(size_t)(kb + ty + i) * NPTS + xb + tx] = h;
        g_wbT_l[(size_t)(kb + ty + i) * NPTS + xb + tx] = l;
    }
}

// bases elementwise split (no transpose needed: B operand is K-major already)
__global__ void __launch_bounds__(256) tbs_kernel(const float* __restrict__ bases) {
    int i4 = blockIdx.x * 256 + threadIdx.x;   // 524288 float4s
    float4 v = ((const float4*)bases)[i4];
    uint2 hi, lo;
    cvt_hl(v, hi, lo);
    *(uint2*)&g_bs_h[(size_t)i4 * 4] = hi;
    *(uint2*)&g_bs_l[(size_t)i4 * 4] = lo;
}

// generic fp32 -> hi/lo split for xhatT (SEL=0) and y (SEL=1)
template <int SEL>
__global__ void __launch_bounds__(256) cvt_big_kernel() {
    int i4 = blockIdx.x * 256 + threadIdx.x;   // 65536 float4s
    const float* src = (SEL == 0) ? g_xhatT : g_y;
    bf16* dh = (SEL == 0) ? g_xhT_h : g_y_h;
    bf16* dl = (SEL == 0) ? g_xhT_l : g_y_l;
    float4 v = ((const float4*)src)[i4];
    uint2 hi, lo;
    cvt_hl(v, hi, lo);
    *(uint2*)&dh[(size_t)i4 * 4] = hi;
    *(uint2*)&dl[(size_t)i4 * 4] = lo;
}

// ---------------- GEMM stage kernels ----------------
// stage A: xhatT[b][l][i] += x[(b,i),:] @ wbT  (16 b-blocks x 16 K-splits)
__global__ void __launch_bounds__(256) k_mm_a(const float* __restrict__ x) {
    const int b  = blockIdx.x;
    const int ks = blockIdx.y;                 // 16 splits x 1024 K
    float acc[16][4];
    mm_af32_core(x + (size_t)(b * 128) * NPTS + ks * 1024, NPTS,
                 g_wbT_h + ks * 1024, g_wbT_l + ks * 1024, NPTS, 32, acc);
    const int lane = threadIdx.x & 31, w = threadIdx.x >> 5;
    const int wr = w >> 2, wc = w & 3;
    float* dst = g_xhatT + (size_t)b * 16384;
#pragma unroll
    for (int mi = 0; mi < 4; ++mi)
#pragma unroll
        for (int ni = 0; ni < 4; ++ni) {
            const int row = wr * 64 + mi * 16 + (lane >> 2);   // i
            const int col = wc * 32 + ni * 8 + (lane & 3) * 2; // l
            const float* a = acc[mi * 4 + ni];
            atomicAdd(&dst[(col + 0) * 128 + row],     a[0]);
            atomicAdd(&dst[(col + 1) * 128 + row],     a[1]);
            atomicAdd(&dst[(col + 0) * 128 + row + 8], a[2]);
            atomicAdd(&dst[(col + 1) * 128 + row + 8], a[3]);
        }
}

// stage Z: z[(b,o)][(j,l)] = Wt[j] @ xhatT[b]^T, stored pre-split bf16
__global__ void __launch_bounds__(256) k_mm_z() {
    const int b = blockIdx.x >> 4, j = blockIdx.x & 15;
    float acc[16][4];
    mm_bf16_core(g_Wt_h + (size_t)j * 16384, g_Wt_l + (size_t)j * 16384, 128,
                 g_xhT_h + (size_t)b * 16384, g_xhT_l + (size_t)b * 16384, 128, 4, acc);
    const int lane = threadIdx.x & 31, w = threadIdx.x >> 5;
    const int wr = w >> 2, wc = w & 3;
#pragma unroll
    for (int mi = 0; mi < 4; ++mi)
#pragma unroll
        for (int ni = 0; ni < 4; ++ni) {
            const int row = wr * 64 + mi * 16 + (lane >> 2);   // o
            const int col = wc * 32 + ni * 8 + (lane & 3) * 2; // l
            const float* a = acc[mi * 4 + ni];
            uint32_t hw, lw;
            size_t idx0 = (size_t)(b * 128 + row) * 2048 + j * 128 + col;
            split2(a[0], a[1], hw, lw);
            *(uint32_t*)&g_z_h[idx0] = hw;
            *(uint32_t*)&g_z_l[idx0] = lw;
            size_t idx1 = idx0 + (size_t)8 * 2048;
            split2(a[2], a[3], hw, lw);
            *(uint32_t*)&g_z_h[idx1] = hw;
            *(uint32_t*)&g_z_l[idx1] = lw;
        }
}

// stage Y: y[(b,o)][k] += z @ Hk   (16 row-blocks x 8 K-splits of 8 ktiles)
__global__ void __launch_bounds__(256) k_mm_y() {
    const int row0 = blockIdx.x * 128;
    const int kt0  = blockIdx.y * 8;
    float acc[16][4];
    mm_bf16_core(g_z_h + (size_t)row0 * 2048 + kt0 * KT,
                 g_z_l + (size_t)row0 * 2048 + kt0 * KT, 2048,
                 g_Hk_h + kt0 * KT, g_Hk_l + kt0 * KT, 2048, 8, acc);
    const int lane = threadIdx.x & 31, w = threadIdx.x >> 5;
    const int wr = w >> 2, wc = w & 3;
#pragma unroll
    for (int mi = 0; mi < 4; ++mi)
#pragma unroll
        for (int ni = 0; ni < 4; ++ni) {
            const int row = row0 + wr * 64 + mi * 16 + (lane >> 2);
            const int col = wc * 32 + ni * 8 + (lane & 3) * 2;
            const float* a = acc[mi * 4 + ni];
            atomicAdd(&g_y[(size_t)row * 128 + col],           a[0]);
            atomicAdd(&g_y[(size_t)row * 128 + col + 1],       a[1]);
            atomicAdd(&g_y[(size_t)(row + 8) * 128 + col],     a[2]);
            atomicAdd(&g_y[(size_t)(row + 8) * 128 + col + 1], a[3]);
        }
}

// stage D: out[2048,16384] = y @ bases^T
__global__ void __launch_bounds__(256) k_mm_d(float* __restrict__ out) {
    const int row0 = blockIdx.x * 128;
    const int x0   = blockIdx.y * 128;
    float acc[16][4];
    mm_bf16_core(g_y_h + (size_t)row0 * 128, g_y_l + (size_t)row0 * 128, 128,
                 g_bs_h + (size_t)x0 * 128, g_bs_l + (size_t)x0 * 128, 128, 4, acc);
    const int lane = threadIdx.x & 31, w = threadIdx.x >> 5;
    const int wr = w >> 2, wc = w & 3;
#pragma unroll
    for (int mi = 0; mi < 4; ++mi)
#pragma unroll
        for (int ni = 0; ni < 4; ++ni) {
            const int row = row0 + wr * 64 + mi * 16 + (lane >> 2);
            const int col = x0 + wc * 32 + ni * 8 + (lane & 3) * 2;
            const float* a = acc[mi * 4 + ni];
            *(float2*)&out[(size_t)row * NPTS + col]       = make_float2(a[0], a[1]);
            *(float2*)&out[(size_t)(row + 8) * NPTS + col] = make_float2(a[2], a[3]);
        }
}

// ---------------- launch ----------------
extern "C" void kernel_launch(void* const* d_in, const int* in_sizes, int n_in,
                              void* d_out, int out_size) {
    const float* x       = (const float*)d_in[0];
    const float* bases   = (const float*)d_in[1];
    const float* wbases  = (const float*)d_in[2];
    const float* product = (const float*)d_in[3];
    const float* Dout    = (const float*)d_in[4];
    const float* Din     = (const float*)d_in[5];
    const float* Aop     = (const float*)d_in[6];
    const float* Bop     = (const float*)d_in[7];
    const float* weights = (const float*)d_in[8];
    float* out = (float*)d_out;

    cudaFuncSetAttribute(k_mm_a, cudaFuncAttributeMaxDynamicSharedMemorySize, SMEM_B);
    cudaFuncSetAttribute(k_mm_z, cudaFuncAttributeMaxDynamicSharedMemorySize, SMEM_B);
    cudaFuncSetAttribute(k_mm_y, cudaFuncAttributeMaxDynamicSharedMemorySize, SMEM_B);
    cudaFuncSetAttribute(k_mm_d, cudaFuncAttributeMaxDynamicSharedMemorySize, SMEM_B);

    zero_kernel<<<1024, 256>>>();
    ht_kernel<<<NJ, 256>>>(Aop, Bop, Dout, Din, product);
    wt_kernel<<<1024, 256>>>(weights);
    twb_kernel<<<dim3(NPTS / 32, 4), 256>>>(wbases);
    tbs_kernel<<<2048, 256>>>(bases);

    k_mm_a<<<dim3(16, 16), 256, SMEM_B>>>(x);
    cvt_big_kernel<0><<<256, 256>>>();
    k_mm_z<<<NB * NJ, 256, SMEM_B>>>();
    k_mm_y<<<dim3(16, 8), 256, SMEM_B>>>();
    cvt_big_kernel<1><<<256, 256>>>();
    k_mm_d<<<dim3(16, 128), 256, SMEM_B>>>(out);
}

// round 8
// speedup vs baseline: 1.3231x; 1.3231x over previous
#include <cuda_runtime.h>
#include <cuda_fp16.h>
#include <cstdint>

#define NB    16
#define NDIM  128
#define NPTS  16384
#define NJ    16
#define NR    8
#define KT    32                     // K-tile depth
#define ROWPAD 40                    // padded smem row (elements)
#define TILE_B (128 * ROWPAD * 2)    // 10240 bytes per fp16 tile
#define WSCALE 16384.0f
#define WINV   (1.0f / 16384.0f)

typedef __half hf;

// ---------------- device scratch ----------------
__device__ __align__(16) float g_xhatT[NB * 128 * 128];      // [b][l][i]  1 MB
__device__ __align__(16) float g_y    [NB * 128 * 128];      // [(b,o)][k] 1 MB (scaled 2^14)
__device__ __align__(16) hf g_xhT_h[NB * 128 * 128], g_xhT_l[NB * 128 * 128];
__device__ __align__(16) hf g_Wt_h [NJ * 128 * 128], g_Wt_l [NJ * 128 * 128];   // [j][o][i] (x 2^14)
__device__ __align__(16) hf g_Hk_h [128 * NJ * 128], g_Hk_l [128 * NJ * 128];   // [k][(j,l)]
__device__ __align__(16) hf g_z_h  [2048 * 2048],    g_z_l  [2048 * 2048];      // [(b,o)][(j,l)] scaled
__device__ __align__(16) hf g_y_h  [2048 * 128],     g_y_l  [2048 * 128];       // descaled
__device__ __align__(16) hf g_wbT_h[128 * NPTS];                                 // [l][x]
__device__ __align__(16) hf g_bs_h [NPTS * 128];                                 // [x][k]

// ---------------- helpers ----------------
__device__ __forceinline__ uint32_t smem_u32(const void* p) {
    uint32_t a;
    asm("{ .reg .u64 t; cvta.to.shared.u64 t, %1; cvt.u32.u64 %0, t; }" : "=r"(a) : "l"(p));
    return a;
}
__device__ __forceinline__ void cp16(uint32_t dst, const void* src) {
    asm volatile("cp.async.cg.shared.global [%0], [%1], 16;" :: "r"(dst), "l"(src));
}
__device__ __forceinline__ void cp_commit() {
    asm volatile("cp.async.commit_group;" ::: "memory");
}
template <int N>
__device__ __forceinline__ void cp_wait() {
    asm volatile("cp.async.wait_group %0;" :: "n"(N) : "memory");
}
__device__ __forceinline__ void ldmx4(uint32_t* r, uint32_t addr) {
    asm volatile("ldmatrix.sync.aligned.m8n8.x4.shared.b16 {%0,%1,%2,%3}, [%4];"
                 : "=r"(r[0]), "=r"(r[1]), "=r"(r[2]), "=r"(r[3]) : "r"(addr));
}
__device__ __forceinline__ void mma_f16(float* c, const uint32_t* a, const uint32_t* b) {
    asm volatile("mma.sync.aligned.m16n8k16.row.col.f32.f16.f16.f32 "
                 "{%0,%1,%2,%3}, {%4,%5,%6,%7}, {%8,%9}, {%0,%1,%2,%3};"
                 : "+f"(c[0]), "+f"(c[1]), "+f"(c[2]), "+f"(c[3])
                 : "r"(a[0]), "r"(a[1]), "r"(a[2]), "r"(a[3]), "r"(b[0]), "r"(b[1]));
}
// fp32x4 -> fp16x2 pair (hi only)
__device__ __forceinline__ uint2 cvt_h4(float4 v) {
    __half2 h0 = __floats2half2_rn(v.x, v.y);
    __half2 h1 = __floats2half2_rn(v.z, v.w);
    return make_uint2(*(uint32_t*)&h0, *(uint32_t*)&h1);
}
// fp32x4 -> hi + lo residual pairs
__device__ __forceinline__ void cvt_hl4(float4 v, uint2& hi, uint2& lo) {
    __half2 h0 = __floats2half2_rn(v.x, v.y);
    __half2 h1 = __floats2half2_rn(v.z, v.w);
    float rx = v.x - __low2float(h0),  ry = v.y - __high2float(h0);
    float rz = v.z - __low2float(h1),  rw = v.w - __high2float(h1);
    __half2 l0 = __floats2half2_rn(rx, ry);
    __half2 l1 = __floats2half2_rn(rz, rw);
    hi = make_uint2(*(uint32_t*)&h0, *(uint32_t*)&h1);
    lo = make_uint2(*(uint32_t*)&l0, *(uint32_t*)&l1);
}
__device__ __forceinline__ void split1(float v, hf& h, hf& l) {
    h = __float2half_rn(v);
    l = __float2half_rn(v - __half2float(h));
}
__device__ __forceinline__ void split2(float a, float b, uint32_t& hw, uint32_t& lw) {
    __half2 h = __floats2half2_rn(a, b);
    float ra = a - __low2float(h), rb = b - __high2float(h);
    __half2 l = __floats2half2_rn(ra, rb);
    hw = *(uint32_t*)&h;
    lw = *(uint32_t*)&l;
}

// ---------------- tile slot layout per TERMS ----------------
// TERMS==1: [Ah, Bh]            NT=2
// TERMS==2: [Ah, Al, Bh]        NT=3   (full-A x Bh)
// TERMS==3: [Ah, Al, Bh, Bl]    NT=4
template <int TERMS> struct Slots {
    static constexpr int SAh = 0;
    static constexpr int SAl = 1;                       // valid TERMS>=2
    static constexpr int SBh = (TERMS == 1) ? 1 : 2;
    static constexpr int SBl = 3;                       // valid TERMS==3
    static constexpr int NT  = (TERMS == 1) ? 2 : (TERMS == 2) ? 3 : 4;
    static constexpr int BUF = NT * TILE_B;
};

// ---------------- compute one 32-deep K tile ----------------
template <int TERMS>
__device__ __forceinline__ void compute_kt(uint32_t bb, float acc[16][4],
                                           int a_off, int b_off, int wr, int wc) {
    using S = Slots<TERMS>;
#pragma unroll
    for (int ks = 0; ks < 2; ++ks) {
        const uint32_t koff = ks * 32;
        uint32_t bh[4][2], bl[4][2];
#pragma unroll
        for (int n2 = 0; n2 < 2; ++n2) {
            const uint32_t nbase = (wc * 32 + n2 * 16) * 80 + koff + b_off;
            uint32_t r4[4];
            ldmx4(r4, bb + S::SBh * TILE_B + nbase);
            bh[n2 * 2][0] = r4[0]; bh[n2 * 2][1] = r4[1];
            bh[n2 * 2 + 1][0] = r4[2]; bh[n2 * 2 + 1][1] = r4[3];
            if (TERMS == 3) {
                ldmx4(r4, bb + S::SBl * TILE_B + nbase);
                bl[n2 * 2][0] = r4[0]; bl[n2 * 2][1] = r4[1];
                bl[n2 * 2 + 1][0] = r4[2]; bl[n2 * 2 + 1][1] = r4[3];
            }
        }
#pragma unroll
        for (int mi = 0; mi < 4; ++mi) {
            const uint32_t mbase = (wr * 64 + mi * 16) * 80 + koff + a_off;
            uint32_t ah[4], al[4];
            ldmx4(ah, bb + S::SAh * TILE_B + mbase);
            if (TERMS >= 2) ldmx4(al, bb + S::SAl * TILE_B + mbase);
#pragma unroll
            for (int ni = 0; ni < 4; ++ni) {
                mma_f16(acc[mi * 4 + ni], ah, bh[ni]);
                if (TERMS >= 2) mma_f16(acc[mi * 4 + ni], al, bh[ni]);
                if (TERMS == 3) mma_f16(acc[mi * 4 + ni], ah, bl[ni]);
            }
        }
    }
}

// issue cp.async for one fp16 tile (2x16B chunks/thread; 64B data per 80B row)
__device__ __forceinline__ void issue_tile(uint32_t bb, int tile, const hf* base,
                                           int ld, int k0, int t) {
    int row = t >> 2, q = t & 3;
    cp16(bb + tile * TILE_B + row * 80 + q * 16, base + (size_t)row * ld + k0 + q * 8);
    row = (t + 256) >> 2; q = (t + 256) & 3;
    cp16(bb + tile * TILE_B + row * 80 + q * 16, base + (size_t)row * ld + k0 + q * 8);
}

// ---------------- pre-split fp16 core (TERMS = 2 or 3) ----------------
template <int TERMS>
__device__ __forceinline__ void mm_f16_core(const hf* __restrict__ Ah,
                                            const hf* __restrict__ Al, int lda,
                                            const hf* __restrict__ Bh,
                                            const hf* __restrict__ Bl, int ldb,
                                            int ktiles, float acc[16][4]) {
    using S = Slots<TERMS>;
    extern __shared__ __align__(128) char dsm[];
    const int t = threadIdx.x, lane = t & 31, w = t >> 5;
    const int wr = w >> 2, wc = w & 3;
    const uint32_t sb = smem_u32(dsm);
    const int a_off = ((lane & 7) + ((lane >> 3) & 1) * 8) * 80 + ((lane >> 4) & 1) * 16;
    const int b_off = ((lane & 7) + ((lane >> 4) & 1) * 8) * 80 + ((lane >> 3) & 1) * 16;

#pragma unroll
    for (int i = 0; i < 16; ++i)
#pragma unroll
        for (int j = 0; j < 4; ++j) acc[i][j] = 0.0f;

    issue_tile(sb, S::SAh, Ah, lda, 0, t);
    if (TERMS >= 2) issue_tile(sb, S::SAl, Al, lda, 0, t);
    issue_tile(sb, S::SBh, Bh, ldb, 0, t);
    if (TERMS == 3) issue_tile(sb, S::SBl, Bl, ldb, 0, t);
    cp_commit();

    int cur = 0;
    for (int kt = 0; kt < ktiles; ++kt) {
        const bool more = (kt + 1 < ktiles);
        if (more) {
            const uint32_t nb = sb + (cur ^ 1) * S::BUF;
            const int k0 = (kt + 1) * KT;
            issue_tile(nb, S::SAh, Ah, lda, k0, t);
            if (TERMS >= 2) issue_tile(nb, S::SAl, Al, lda, k0, t);
            issue_tile(nb, S::SBh, Bh, ldb, k0, t);
            if (TERMS == 3) issue_tile(nb, S::SBl, Bl, ldb, k0, t);
            cp_commit();
            cp_wait<1>();
        } else {
            cp_wait<0>();
        }
        __syncthreads();
        compute_kt<TERMS>(sb + cur * S::BUF, acc, a_off, b_off, wr, wc);
        __syncthreads();
        cur ^= 1;
    }
}

// ---------------- stage-A core: single term, A fp32 in-kernel cvt ----------------
__device__ __forceinline__ void mm_a_core(const float* __restrict__ A, int lda,
                                          const hf* __restrict__ Bh, int ldb,
                                          int ktiles, float acc[16][4]) {
    using S = Slots<1>;
    extern __shared__ __align__(128) char dsm[];
    const int t = threadIdx.x, lane = t & 31, w = t >> 5;
    const int wr = w >> 2, wc = w & 3;
    const uint32_t sb = smem_u32(dsm);
    const int a_off = ((lane & 7) + ((lane >> 3) & 1) * 8) * 80 + ((lane >> 4) & 1) * 16;
    const int b_off = ((lane & 7) + ((lane >> 4) & 1) * 8) * 80 + ((lane >> 3) & 1) * 16;

#pragma unroll
    for (int i = 0; i < 16; ++i)
#pragma unroll
        for (int j = 0; j < 4; ++j) acc[i][j] = 0.0f;

    float4 av[4];
    issue_tile(sb, S::SBh, Bh, ldb, 0, t);
    cp_commit();
#pragma unroll
    for (int i = 0; i < 4; ++i) {
        const int idx = t + 256 * i, r = idx >> 3, c4 = (idx & 7) << 2;
        av[i] = *(const float4*)&A[(size_t)r * lda + c4];
    }
#pragma unroll
    for (int i = 0; i < 4; ++i) {
        const int idx = t + 256 * i, r = idx >> 3, c4 = (idx & 7) << 2;
        *(uint2*)(dsm + S::SAh * TILE_B + r * 80 + c4 * 2) = cvt_h4(av[i]);
    }

    int cur = 0;
    for (int kt = 0; kt < ktiles; ++kt) {
        const bool more = (kt + 1 < ktiles);
        if (more) {
#pragma unroll
            for (int i = 0; i < 4; ++i) {
                const int idx = t + 256 * i, r = idx >> 3, c4 = (idx & 7) << 2;
                av[i] = *(const float4*)&A[(size_t)r * lda + (kt + 1) * KT + c4];
            }
            issue_tile(sb + (cur ^ 1) * S::BUF, S::SBh, Bh, ldb, (kt + 1) * KT, t);
            cp_commit();
            cp_wait<1>();
        } else {
            cp_wait<0>();
        }
        __syncthreads();
        compute_kt<1>(sb + cur * S::BUF, acc, a_off, b_off, wr, wc);
        __syncthreads();
        if (more) {
#pragma unroll
            for (int i = 0; i < 4; ++i) {
                const int idx = t + 256 * i, r = idx >> 3, c4 = (idx & 7) << 2;
                *(uint2*)(dsm + (cur ^ 1) * S::BUF + S::SAh * TILE_B + r * 80 + c4 * 2) =
                    cvt_h4(av[i]);
            }
        }
        cur ^= 1;
    }
}

// ---------------- prep kernels ----------------
__global__ void zero_kernel() {
    int i = blockIdx.x * 256 + threadIdx.x;   // 262144 each
    g_xhatT[i] = 0.0f;
    g_y[i]     = 0.0f;
}

__global__ void __launch_bounds__(256) ht_kernel(const float* __restrict__ Aop,
                                                 const float* __restrict__ Bop,
                                                 const float* __restrict__ Dout,
                                                 const float* __restrict__ Din,
                                                 const float* __restrict__ product) {
    int j = blockIdx.x;
    int t = threadIdx.x;
    __shared__ float Aj[NR * 64];
    __shared__ float Bj[NR * 64];
    __shared__ float Qs[64 * 64];
    for (int i = t; i < NR * 64; i += 256) {
        Aj[i] = Aop[j * (NR * 64) + i];
        Bj[i] = Bop[j * (NR * 64) + i];
    }
    __syncthreads();
#pragma unroll
    for (int s = 0; s < 16; ++s) {
        int idx = t + 256 * s;
        int m = idx >> 6, n = idx & 63;
        float q = 0.0f;
#pragma unroll
        for (int r = 0; r < NR; ++r) q += Aj[r * 64 + m] * Bj[r * 64 + n];
        Qs[idx] = q;
    }
    __syncthreads();
#pragma unroll 4
    for (int s = 0; s < 64; ++s) {
        int idx = t + 256 * s;        // 16384 = 128x128
        int k = idx >> 7, l = idx & 127;
        float h = Dout[j * 128 + k] * Din[j * 128 + l] * product[k * 128 + l];
        if (k < 64 && l < 64) h += Qs[k * 64 + l];
        hf hh, ll;
        split1(h, hh, ll);
        g_Hk_h[k * (NJ * 128) + j * 128 + l] = hh;
        g_Hk_l[k * (NJ * 128) + j * 128 + l] = ll;
    }
}

__global__ void wt_kernel(const float* __restrict__ w) {
    int id = blockIdx.x * 256 + threadIdx.x;   // 262144
    int ii = id & 127;
    int o  = (id >> 7) & 127;
    int j  = id >> 14;
    hf h, l;
    split1(w[(ii * 128 + o) * NJ + j] * WSCALE, h, l);
    g_Wt_h[id] = h;
    g_Wt_l[id] = l;
}

// wbases[NPTS][128] -> wbT_h [128][NPTS] (fp16, single)
__global__ void __launch_bounds__(256) twb_kernel(const float* __restrict__ wb) {
    __shared__ float tile[32][33];
    int xb = blockIdx.x * 32, kb = blockIdx.y * 32;
    int tx = threadIdx.x & 31, ty = threadIdx.x >> 5;
#pragma unroll
    for (int i = 0; i < 32; i += 8)
        tile[ty + i][tx] = wb[(size_t)(xb + ty + i) * 128 + kb + tx];
    __syncthreads();
#pragma unroll
    for (int i = 0; i < 32; i += 8)
        g_wbT_h[(size_t)(kb + ty + i) * NPTS + xb + tx] = __float2half_rn(tile[tx][ty + i]);
}

// bases elementwise -> fp16 (single)
__global__ void __launch_bounds__(256) tbs_kernel(const float* __restrict__ bases) {
    int i4 = blockIdx.x * 256 + threadIdx.x;   // 524288 float4s
    float4 v = ((const float4*)bases)[i4];
    *(uint2*)&g_bs_h[(size_t)i4 * 4] = cvt_h4(v);
}

// fp32 -> hi/lo split for xhatT (SEL=0) and y (SEL=1, descale)
template <int SEL>
__global__ void __launch_bounds__(256) cvt_big_kernel() {
    int i4 = blockIdx.x * 256 + threadIdx.x;   // 65536 float4s
    const float* src = (SEL == 0) ? g_xhatT : g_y;
    hf* dh = (SEL == 0) ? g_xhT_h : g_y_h;
    hf* dl = (SEL == 0) ? g_xhT_l : g_y_l;
    float4 v = ((const float4*)src)[i4];
    if (SEL == 1) { v.x *= WINV; v.y *= WINV; v.z *= WINV; v.w *= WINV; }
    uint2 hi, lo;
    cvt_hl4(v, hi, lo);
    *(uint2*)&dh[(size_t)i4 * 4] = hi;
    *(uint2*)&dl[(size_t)i4 * 4] = lo;
}

// ---------------- GEMM stage kernels ----------------
// stage A: xhatT[b][l][i] += x[(b,i),:] @ wbT  (16 b-blocks x 16 K-splits, 1-term)
__global__ void __launch_bounds__(256) k_mm_a(const float* __restrict__ x) {
    const int b  = blockIdx.x;
    const int ks = blockIdx.y;                 // 16 splits x 1024 K
    float acc[16][4];
    mm_a_core(x + (size_t)(b * 128) * NPTS + ks * 1024, NPTS,
              g_wbT_h + ks * 1024, NPTS, 32, acc);
    const int lane = threadIdx.x & 31, w = threadIdx.x >> 5;
    const int wr = w >> 2, wc = w & 3;
    float* dst = g_xhatT + (size_t)b * 16384;
#pragma unroll
    for (int mi = 0; mi < 4; ++mi)
#pragma unroll
        for (int ni = 0; ni < 4; ++ni) {
            const int row = wr * 64 + mi * 16 + (lane >> 2);   // i
            const int col = wc * 32 + ni * 8 + (lane & 3) * 2; // l
            const float* a = acc[mi * 4 + ni];
            atomicAdd(&dst[(col + 0) * 128 + row],     a[0]);
            atomicAdd(&dst[(col + 1) * 128 + row],     a[1]);
            atomicAdd(&dst[(col + 0) * 128 + row + 8], a[2]);
            atomicAdd(&dst[(col + 1) * 128 + row + 8], a[3]);
        }
}

// stage Z: z[(b,o)][(j,l)] = Wt'[j] @ xhatT[b]^T (3-term), stored split fp16
__global__ void __launch_bounds__(256) k_mm_z() {
    const int b = blockIdx.x >> 4, j = blockIdx.x & 15;
    float acc[16][4];
    mm_f16_core<3>(g_Wt_h + (size_t)j * 16384, g_Wt_l + (size_t)j * 16384, 128,
                   g_xhT_h + (size_t)b * 16384, g_xhT_l + (size_t)b * 16384, 128, 4, acc);
    const int lane = threadIdx.x & 31, w = threadIdx.x >> 5;
    const int wr = w >> 2, wc = w & 3;
#pragma unroll
    for (int mi = 0; mi < 4; ++mi)
#pragma unroll
        for (int ni = 0; ni < 4; ++ni) {
            const int row = wr * 64 + mi * 16 + (lane >> 2);   // o
            const int col = wc * 32 + ni * 8 + (lane & 3) * 2; // l
            const float* a = acc[mi * 4 + ni];
            uint32_t hw, lw;
            size_t idx0 = (size_t)(b * 128 + row) * 2048 + j * 128 + col;
            split2(a[0], a[1], hw, lw);
            *(uint32_t*)&g_z_h[idx0] = hw;
            *(uint32_t*)&g_z_l[idx0] = lw;
            size_t idx1 = idx0 + (size_t)8 * 2048;
            split2(a[2], a[3], hw, lw);
            *(uint32_t*)&g_z_h[idx1] = hw;
            *(uint32_t*)&g_z_l[idx1] = lw;
        }
}

// stage Y: y[(b,o)][k] += z @ Hk (3-term; 16 row-blocks x 8 K-splits)
__global__ void __launch_bounds__(256) k_mm_y() {
    const int row0 = blockIdx.x * 128;
    const int kt0  = blockIdx.y * 8;
    float acc[16][4];
    mm_f16_core<3>(g_z_h + (size_t)row0 * 2048 + kt0 * KT,
                   g_z_l + (size_t)row0 * 2048 + kt0 * KT, 2048,
                   g_Hk_h + kt0 * KT, g_Hk_l + kt0 * KT, 2048, 8, acc);
    const int lane = threadIdx.x & 31, w = threadIdx.x >> 5;
    const int wr = w >> 2, wc = w & 3;
#pragma unroll
    for (int mi = 0; mi < 4; ++mi)
#pragma unroll
        for (int ni = 0; ni < 4; ++ni) {
            const int row = row0 + wr * 64 + mi * 16 + (lane >> 2);
            const int col = wc * 32 + ni * 8 + (lane & 3) * 2;
            const float* a = acc[mi * 4 + ni];
            atomicAdd(&g_y[(size_t)row * 128 + col],           a[0]);
            atomicAdd(&g_y[(size_t)row * 128 + col + 1],       a[1]);
            atomicAdd(&g_y[(size_t)(row + 8) * 128 + col],     a[2]);
            atomicAdd(&g_y[(size_t)(row + 8) * 128 + col + 1], a[3]);
        }
}

// stage D: out = (yh+yl) @ bases_h^T (2-term)
__global__ void __launch_bounds__(256) k_mm_d(float* __restrict__ out) {
    const int row0 = blockIdx.x * 128;
    const int x0   = blockIdx.y * 128;
    float acc[16][4];
    mm_f16_core<2>(g_y_h + (size_t)row0 * 128, g_y_l + (size_t)row0 * 128, 128,
                   g_bs_h + (size_t)x0 * 128, (const hf*)nullptr, 128, 4, acc);
    const int lane = threadIdx.x & 31, w = threadIdx.x >> 5;
    const int wr = w >> 2, wc = w & 3;
#pragma unroll
    for (int mi = 0; mi < 4; ++mi)
#pragma unroll
        for (int ni = 0; ni < 4; ++ni) {
            const int row = row0 + wr * 64 + mi * 16 + (lane >> 2);
            const int col = x0 + wc * 32 + ni * 8 + (lane & 3) * 2;
            const float* a = acc[mi * 4 + ni];
            *(float2*)&out[(size_t)row * NPTS + col]       = make_float2(a[0], a[1]);
            *(float2*)&out[(size_t)(row + 8) * NPTS + col] = make_float2(a[2], a[3]);
        }
}

// ---------------- launch ----------------
extern "C" void kernel_launch(void* const* d_in, const int* in_sizes, int n_in,
                              void* d_out, int out_size) {
    const float* x       = (const float*)d_in[0];
    const float* bases   = (const float*)d_in[1];
    const float* wbases  = (const float*)d_in[2];
    const float* product = (const float*)d_in[3];
    const float* Dout    = (const float*)d_in[4];
    const float* Din     = (const float*)d_in[5];
    const float* Aop     = (const float*)d_in[6];
    const float* Bop     = (const float*)d_in[7];
    const float* weights = (const float*)d_in[8];
    float* out = (float*)d_out;

    const int SM_A = 2 * Slots<1>::BUF;   // 40960
    const int SM_D = 2 * Slots<2>::BUF;   // 61440
    const int SM_3 = 2 * Slots<3>::BUF;   // 81920
    cudaFuncSetAttribute(k_mm_a, cudaFuncAttributeMaxDynamicSharedMemorySize, SM_A);
    cudaFuncSetAttribute(k_mm_z, cudaFuncAttributeMaxDynamicSharedMemorySize, SM_3);
    cudaFuncSetAttribute(k_mm_y, cudaFuncAttributeMaxDynamicSharedMemorySize, SM_3);
    cudaFuncSetAttribute(k_mm_d, cudaFuncAttributeMaxDynamicSharedMemorySize, SM_D);

    zero_kernel<<<1024, 256>>>();
    ht_kernel<<<NJ, 256>>>(Aop, Bop, Dout, Din, product);
    wt_kernel<<<1024, 256>>>(weights);
    twb_kernel<<<dim3(NPTS / 32, 4), 256>>>(wbases);
    tbs_kernel<<<2048, 256>>>(bases);

    k_mm_a<<<dim3(16, 16), 256, SM_A>>>(x);
    cvt_big_kernel<0><<<256, 256>>>();
    k_mm_z<<<NB * NJ, 256, SM_3>>>();
    k_mm_y<<<dim3(16, 8), 256, SM_3>>>();
    cvt_big_kernel<1><<<256, 256>>>();
    k_mm_d<<<dim3(16, 128), 256, SM_D>>>(out);
}